// round 7
// baseline (speedup 1.0000x reference)
#include <cuda_runtime.h>
#include <cstddef>

// BilinearMixture: out[e,c] = sum_w (sum_d u[ui,d]*W[w,d]*v[vi,d]) * scalars[w,c]
//                           + u_bias[ui,c] + v_bias[vi,c]
// E=2e6, D=128, NUM_W=3, C=5.
//
// R5 shape (8 lanes/edge, 2 quads = 8 edges/warp, MLP 16) plus L2 policy via
// createpolicy + ld.global.nc.L2::cache_hint (the inline .L2::evict_last
// modifier is rejected by sm_103a ptxas for .v4.f32):
//   - feature/bias gathers:  evict_last  (keep 102MB tables L2-resident)
//   - output stores:         st.global.cs (evict-first; don't thrash L2)

#define D 128
#define NUM_W 3
#define NUM_C 5
#define THREADS 256
#define WARPS_PER_BLOCK (THREADS / 32)
#define EDGES_PER_WARP 8
#define EDGES_PER_BLOCK (WARPS_PER_BLOCK * EDGES_PER_WARP)  // 64

__device__ __forceinline__ unsigned long long mk_policy_el() {
    unsigned long long pol;
    asm("createpolicy.fractional.L2::evict_last.b64 %0, 1.0;" : "=l"(pol));
    return pol;
}
__device__ __forceinline__ float4 ldg_el(const float4* p, unsigned long long pol) {
    float4 r;
    asm("ld.global.nc.L2::cache_hint.v4.f32 {%0,%1,%2,%3}, [%4], %5;"
        : "=f"(r.x), "=f"(r.y), "=f"(r.z), "=f"(r.w) : "l"(p), "l"(pol));
    return r;
}
__device__ __forceinline__ float ldg_el_f(const float* p, unsigned long long pol) {
    float r;
    asm("ld.global.nc.L2::cache_hint.f32 %0, [%1], %2;" : "=f"(r) : "l"(p), "l"(pol));
    return r;
}

__global__ __launch_bounds__(THREADS, 2)
void bilinear_mixture_kernel(
    const float* __restrict__ u_feats,
    const float* __restrict__ v_feats,
    const int*   __restrict__ u_idx,
    const int*   __restrict__ v_idx,
    const float* __restrict__ W,
    const float* __restrict__ scalars,
    const float* __restrict__ u_bias,
    const float* __restrict__ v_bias,
    float*       __restrict__ out,
    int E)
{
    const int tid  = threadIdx.x;
    const int lane = tid & 31;
    const int l    = lane & 7;        // lane within edge-group (0..7)
    const int g    = lane >> 3;       // edge-group within warp (0..3)
    const int warp = tid >> 5;

    const unsigned long long pol = mk_policy_el();

    const int ebase = blockIdx.x * EDGES_PER_BLOCK + warp * EDGES_PER_WARP;
    const int e0 = ebase + g;       // quad A edge
    const int e1 = ebase + 4 + g;   // quad B edge
    const bool val0 = (e0 < E);
    const bool val1 = (e1 < E);

    const int ui0 = val0 ? u_idx[e0] : 0;
    const int vi0 = val0 ? v_idx[e0] : 0;
    const int ui1 = val1 ? u_idx[e1] : 0;
    const int vi1 = val1 ? v_idx[e1] : 0;

    const float4* __restrict__ uf = reinterpret_cast<const float4*>(u_feats);
    const float4* __restrict__ vf = reinterpret_cast<const float4*>(v_feats);
    const float4* up0 = uf + (size_t)ui0 * (D / 4);
    const float4* vp0 = vf + (size_t)vi0 * (D / 4);
    const float4* up1 = uf + (size_t)ui1 * (D / 4);
    const float4* vp1 = vf + (size_t)vi1 * (D / 4);

    // Issue all 16 feature loads up front: MLP = 16 per warp slot.
    float4 ua[4], va[4], ub4[4], vb4[4];
#pragma unroll
    for (int i = 0; i < 4; i++) {
        ua[i]  = ldg_el(up0 + i * 8 + l, pol);
        va[i]  = ldg_el(vp0 + i * 8 + l, pol);
        ub4[i] = ldg_el(up1 + i * 8 + l, pol);
        vb4[i] = ldg_el(vp1 + i * 8 + l, pol);
    }

    // Per-class constants + bias gathers (overlap with outstanding loads).
    float s0 = 0.f, s1 = 0.f, s2 = 0.f;
    float ubias0 = 0.f, vbias0 = 0.f, ubias1 = 0.f, vbias1 = 0.f;
    if (l < NUM_C) {
        s0 = __ldg(scalars + 0 * NUM_C + l);
        s1 = __ldg(scalars + 1 * NUM_C + l);
        s2 = __ldg(scalars + 2 * NUM_C + l);
        ubias0 = ldg_el_f(u_bias + (size_t)ui0 * NUM_C + l, pol);
        vbias0 = ldg_el_f(v_bias + (size_t)vi0 * NUM_C + l, pol);
        ubias1 = ldg_el_f(u_bias + (size_t)ui1 * NUM_C + l, pol);
        vbias1 = ldg_el_f(v_bias + (size_t)vi1 * NUM_C + l, pol);
    }

    const float4* __restrict__ Wp = reinterpret_cast<const float4*>(W);

    float a0 = 0.f, a1 = 0.f, a2 = 0.f;   // quad A bases
    float c0 = 0.f, c1 = 0.f, c2 = 0.f;   // quad B bases
#pragma unroll
    for (int i = 0; i < 4; i++) {
        // Broadcast W loads (1 wf each, L1-hit), reused by both quads.
        const float4 w0 = __ldg(Wp + 0 * (D / 4) + i * 8 + l);
        const float4 w1 = __ldg(Wp + 1 * (D / 4) + i * 8 + l);
        const float4 w2 = __ldg(Wp + 2 * (D / 4) + i * 8 + l);

        {
            const float p0 = ua[i].x * va[i].x;
            const float p1 = ua[i].y * va[i].y;
            const float p2 = ua[i].z * va[i].z;
            const float p3 = ua[i].w * va[i].w;
            a0 = fmaf(p0, w0.x, fmaf(p1, w0.y, fmaf(p2, w0.z, fmaf(p3, w0.w, a0))));
            a1 = fmaf(p0, w1.x, fmaf(p1, w1.y, fmaf(p2, w1.z, fmaf(p3, w1.w, a1))));
            a2 = fmaf(p0, w2.x, fmaf(p1, w2.y, fmaf(p2, w2.z, fmaf(p3, w2.w, a2))));
        }
        {
            const float p0 = ub4[i].x * vb4[i].x;
            const float p1 = ub4[i].y * vb4[i].y;
            const float p2 = ub4[i].z * vb4[i].z;
            const float p3 = ub4[i].w * vb4[i].w;
            c0 = fmaf(p0, w0.x, fmaf(p1, w0.y, fmaf(p2, w0.z, fmaf(p3, w0.w, c0))));
            c1 = fmaf(p0, w1.x, fmaf(p1, w1.y, fmaf(p2, w1.z, fmaf(p3, w1.w, c1))));
            c2 = fmaf(p0, w2.x, fmaf(p1, w2.y, fmaf(p2, w2.z, fmaf(p3, w2.w, c2))));
        }
    }

    // Butterfly over the 8-lane group: 3 rounds x 6 values (2 quads).
#pragma unroll
    for (int off = 4; off; off >>= 1) {
        a0 += __shfl_xor_sync(0xffffffffu, a0, off);
        a1 += __shfl_xor_sync(0xffffffffu, a1, off);
        a2 += __shfl_xor_sync(0xffffffffu, a2, off);
        c0 += __shfl_xor_sync(0xffffffffu, c0, off);
        c1 += __shfl_xor_sync(0xffffffffu, c1, off);
        c2 += __shfl_xor_sync(0xffffffffu, c2, off);
    }

    if (l < NUM_C) {
        if (val0) {
            float o = fmaf(a0, s0, fmaf(a1, s1, a2 * s2));
            __stcs(out + (size_t)e0 * NUM_C + l, o + ubias0 + vbias0);
        }
        if (val1) {
            float o = fmaf(c0, s0, fmaf(c1, s1, c2 * s2));
            __stcs(out + (size_t)e1 * NUM_C + l, o + ubias1 + vbias1);
        }
    }
}

extern "C" void kernel_launch(void* const* d_in, const int* in_sizes, int n_in,
                              void* d_out, int out_size)
{
    const float* u_feats = (const float*)d_in[0];
    const float* v_feats = (const float*)d_in[1];
    const int*   u_idx   = (const int*)  d_in[2];
    const int*   v_idx   = (const int*)  d_in[3];
    const float* W       = (const float*)d_in[4];
    const float* scalars = (const float*)d_in[5];
    const float* u_bias  = (const float*)d_in[6];
    const float* v_bias  = (const float*)d_in[7];
    float* out = (float*)d_out;

    int E = in_sizes[2];  // u_idx element count
    int blocks = (E + EDGES_PER_BLOCK - 1) / EDGES_PER_BLOCK;
    bilinear_mixture_kernel<<<blocks, THREADS>>>(
        u_feats, v_feats, u_idx, v_idx, W, scalars, u_bias, v_bias, out, E);
}